// round 4
// baseline (speedup 1.0000x reference)
#include <cuda_runtime.h>

#define B_ 32
#define T_ 2048
#define F_ 256
#define S_ 256

// ============================ f32x2 helpers ============================
__device__ __forceinline__ unsigned long long pack2(float a, float b) {
    unsigned long long r;
    asm("mov.b64 %0, {%1, %2};" : "=l"(r) : "f"(a), "f"(b));
    return r;
}
__device__ __forceinline__ void unpack2(unsigned long long v, float& a, float& b) {
    asm("mov.b64 {%0, %1}, %2;" : "=f"(a), "=f"(b) : "l"(v));
}
__device__ __forceinline__ unsigned long long fma2(unsigned long long a, unsigned long long b,
                                                   unsigned long long c) {
    unsigned long long d;
    asm("fma.rn.f32x2 %0, %1, %2, %3;" : "=l"(d) : "l"(a), "l"(b), "l"(c));
    return d;
}
__device__ __forceinline__ unsigned long long add2(unsigned long long a, unsigned long long b) {
    unsigned long long d;
    asm("add.rn.f32x2 %0, %1, %2;" : "=l"(d) : "l"(a), "l"(b));
    return d;
}

// ============================ smem / mbarrier helpers ============================
__device__ __forceinline__ unsigned smem_u32(const void* p) {
    unsigned a;
    asm("{ .reg .u64 t; cvta.to.shared.u64 t, %1; cvt.u32.u64 %0, t; }" : "=r"(a) : "l"(p));
    return a;
}
__device__ __forceinline__ void mbar_init(unsigned addr, unsigned count) {
    asm volatile("mbarrier.init.shared.b64 [%0], %1;" :: "r"(addr), "r"(count) : "memory");
}
__device__ __forceinline__ void mbar_wait_parity(unsigned addr, unsigned parity) {
    asm volatile(
        "{\n\t.reg .pred P;\n\t"
        "WLP_%=:\n\t"
        "mbarrier.try_wait.parity.acquire.cluster.shared::cta.b64 P, [%0], %1, 0x989680;\n\t"
        "@!P bra WLP_%=;\n\t}"
        :: "r"(addr), "r"(parity) : "memory");
}
__device__ __forceinline__ unsigned mapa_u32(unsigned local_addr, unsigned rank) {
    unsigned r;
    asm("mapa.shared::cluster.u32 %0, %1, %2;" : "=r"(r) : "r"(local_addr), "r"(rank));
    return r;
}
// RELEASE at CLUSTER scope: orders the preceding st.shared::cluster data stores
// before the arrival becomes visible to the peer's acquire-wait. (The R2/R3 bug:
// default arrive is .release.cta, which does NOT order cross-CTA stores.)
__device__ __forceinline__ void remote_arrive_release(unsigned raddr) {
    asm volatile("mbarrier.arrive.release.cluster.shared::cluster.b64 _, [%0];"
                 :: "r"(raddr) : "memory");
}
__device__ __forceinline__ void remote_st_v4(unsigned raddr, float a, float b, float c, float d) {
    asm volatile("st.shared::cluster.v4.f32 [%0], {%1, %2, %3, %4};"
                 :: "r"(raddr), "f"(a), "f"(b), "f"(c), "f"(d) : "memory");
}

// ============================ Kernel 1: U = X @ W_x + bias -> out ============================
// [65536,256] @ [256,256], exact fp32 SIMT tiled GEMM. BM=128 BN=64 BK=16, 256 thr.
#define GBM 128
#define GBN 64
#define GBK 16
#define PADA 132
#define PADW 68

__global__ __launch_bounds__(256, 2)
void gemm_u_kernel(const float* __restrict__ X, const float* __restrict__ W,
                   const float* __restrict__ bias, float* __restrict__ out) {
    __shared__ __align__(16) float As[GBK * PADA];
    __shared__ __align__(16) float Ws[GBK * PADW];
    const int tid = threadIdx.x;
    const int r0 = blockIdx.y * GBM;
    const int c0 = blockIdx.x * GBN;
    const int tx = tid & 15, ty = tid >> 4;
    const int mt = ty * 8, ct = tx * 4;
    const float* Wx = W + S_ * S_;   // input-part rows of W

    float acc[8][4];
#pragma unroll
    for (int i = 0; i < 8; i++)
#pragma unroll
        for (int j = 0; j < 4; j++) acc[i][j] = 0.0f;

    for (int k0 = 0; k0 < F_; k0 += GBK) {
#pragma unroll
        for (int jj = 0; jj < 2; jj++) {
            int li = tid + 256 * jj;
            int r = li >> 2, kq = (li & 3) * 4;
            float4 av = *(const float4*)(X + (r0 + r) * F_ + k0 + kq);
            As[(kq + 0) * PADA + r] = av.x;
            As[(kq + 1) * PADA + r] = av.y;
            As[(kq + 2) * PADA + r] = av.z;
            As[(kq + 3) * PADA + r] = av.w;
        }
        {
            int kr = tid >> 4, cq = (tid & 15) * 4;
            *(float4*)(Ws + kr * PADW + cq) = *(const float4*)(Wx + (k0 + kr) * S_ + c0 + cq);
        }
        __syncthreads();
#pragma unroll
        for (int k = 0; k < GBK; k++) {
            float a[8], w[4];
            *(float4*)(a)     = *(const float4*)(As + k * PADA + mt);
            *(float4*)(a + 4) = *(const float4*)(As + k * PADA + mt + 4);
            *(float4*)(w)     = *(const float4*)(Ws + k * PADW + ct);
#pragma unroll
            for (int i = 0; i < 8; i++)
#pragma unroll
                for (int j = 0; j < 4; j++) acc[i][j] += a[i] * w[j];
        }
        __syncthreads();
    }
    float4 bv = *(const float4*)(bias + c0 + ct);
#pragma unroll
    for (int i = 0; i < 8; i++) {
        float4 o;
        o.x = acc[i][0] + bv.x;
        o.y = acc[i][1] + bv.y;
        o.z = acc[i][2] + bv.z;
        o.w = acc[i][3] + bv.w;
        *(float4*)(out + (r0 + mt + i) * S_ + c0 + ct) = o;
    }
}

// ============================ Kernel 2: the recurrence ============================
// state_t = state_{t-1} @ W_s + U_t, in place on out (out pre-filled with U). Exact fp32.
// One 2-CTA cluster per batch; each CTA owns 128 columns of W_s in registers as f32x2
// pairs. 256 threads = (32 col-groups of 4 cols) x (8 k-quarters of 32 k).
// State lives in smem pre-duplicated as (s,s) 8-byte pairs so LDS.128 feeds f32x2 FMA.
// Halves exchanged per step via st.shared::cluster + release.cluster mbarrier arrive.
#define GRP_B 272                 // bytes per 32-k packed group: 32*8 + 16 pad (bank spread)
#define BUF_B (8 * GRP_B)         // one ping-pong state buffer

__global__ __launch_bounds__(256, 1) __cluster_dims__(2, 1, 1)
void recur_kernel(const float* __restrict__ W, float* __restrict__ out, int write_final) {
    __shared__ __align__(16) unsigned char sbuf[2 * BUF_B];
    __shared__ __align__(8)  unsigned long long smbar[2];

    const int tid = threadIdx.x;
    const int rank = blockIdx.x;          // rank within cluster (cluster spans x)
    const int bat = blockIdx.y;
    const int q = tid & 7;                // k-quarter: k in [32q, 32q+32)
    const int cg = tid >> 3;              // column group 0..31
    const int c0 = rank * 128 + cg * 4;   // 4 consecutive output columns

    const unsigned sbase = smem_u32(sbuf);
    const unsigned mbase = smem_u32(smbar);

    // zero both packed state buffers (state_0 = 0), init mbarriers (32 peer arrivals)
    for (int i = tid; i < (2 * BUF_B) / 8; i += 256)
        ((unsigned long long*)sbuf)[i] = 0ull;
    if (tid == 0) { mbar_init(mbase, 32); mbar_init(mbase + 8, 32); }
    __syncthreads();
    asm volatile("barrier.cluster.arrive.aligned;" ::: "memory");

    // load this thread's W_s slice: 32 k x 4 cols, packed as f32x2 (128 regs)
    unsigned long long w01[32], w23[32];
#pragma unroll
    for (int i = 0; i < 32; i++) {
        float4 wv = *(const float4*)(W + (q * 32 + i) * S_ + c0);
        w01[i] = pack2(wv.x, wv.y);
        w23[i] = pack2(wv.z, wv.w);
    }
    asm volatile("barrier.cluster.wait.aligned;" ::: "memory");

    const unsigned peer = rank ^ 1u;
    float* orow = out + bat * (T_ * S_);
    const bool writer = (q == 0);

    float4 uCur = make_float4(0.f, 0.f, 0.f, 0.f);
    if (writer) uCur = *(const float4*)(orow + c0);     // U row 0

    for (int t = 0; t < T_; t++) {
        const int p_read = t & 1;
        const int p_write = p_read ^ 1;
        if (t > 0) {
            const unsigned parity = (unsigned)(((t - 1) >> 1) & 1);
            mbar_wait_parity(mbase + 8u * p_read, parity);
        }
        // prefetch next U row early so the LDG overlaps this step's compute
        float4 uNext = uCur;
        if (writer && (t + 1 < T_)) uNext = *(const float4*)(orow + (t + 1) * S_ + c0);

        // dot: 32 k's x 4 cols via f32x2, state pre-packed (s,s) in smem
        const unsigned rdbase = sbase + (unsigned)(p_read * BUF_B + q * GRP_B);
        unsigned long long a0 = 0, a1 = 0, a2 = 0, a3 = 0;
#pragma unroll
        for (int jj = 0; jj < 16; jj++) {
            unsigned long long s0, s1;
            asm("ld.shared.v2.u64 {%0, %1}, [%2];" : "=l"(s0), "=l"(s1) : "r"(rdbase + jj * 16));
            a0 = fma2(w01[2 * jj],     s0, a0);
            a1 = fma2(w23[2 * jj],     s0, a1);
            a2 = fma2(w01[2 * jj + 1], s1, a2);
            a3 = fma2(w23[2 * jj + 1], s1, a3);
        }
        float f0, f1, f2, f3;
        unpack2(add2(a0, a2), f0, f1);
        unpack2(add2(a1, a3), f2, f3);
        // reduce across the 8 k-quarters (lanes differ in low 3 bits)
#pragma unroll
        for (int off = 4; off > 0; off >>= 1) {
            f0 += __shfl_xor_sync(0xffffffffu, f0, off);
            f1 += __shfl_xor_sync(0xffffffffu, f1, off);
            f2 += __shfl_xor_sync(0xffffffffu, f2, off);
            f3 += __shfl_xor_sync(0xffffffffu, f3, off);
        }

        if (writer) {
            f0 += uCur.x; f1 += uCur.y; f2 += uCur.z; f3 += uCur.w;
            float4 o = make_float4(f0, f1, f2, f3);
            *(float4*)(orow + t * S_ + c0) = o;                       // state output
            if (t == T_ - 1 && write_final)
                *(float4*)(out + B_ * T_ * S_ + bat * S_ + c0) = o;   // final_state tail
            // write own smem (packed, duplicated) + peer via DSMEM, then RELEASE-arrive
            const int g = c0 >> 5, ki = c0 & 31;
            const unsigned waddr = sbase + (unsigned)(p_write * BUF_B + g * GRP_B + ki * 8);
            asm volatile("st.shared.v4.f32 [%0], {%1, %2, %3, %4};"
                         :: "r"(waddr), "f"(f0), "f"(f0), "f"(f1), "f"(f1) : "memory");
            asm volatile("st.shared.v4.f32 [%0], {%1, %2, %3, %4};"
                         :: "r"(waddr + 16), "f"(f2), "f"(f2), "f"(f3), "f"(f3) : "memory");
            const unsigned pdst = mapa_u32(waddr, peer);
            remote_st_v4(pdst,      f0, f0, f1, f1);
            remote_st_v4(pdst + 16, f2, f2, f3, f3);
            remote_arrive_release(mapa_u32(mbase + 8u * p_write, peer));
            uCur = uNext;
        }
        __syncthreads();   // own-half visibility for next step
    }

    // do not exit while peer's in-flight DSMEM stores may target our smem
    asm volatile("barrier.cluster.arrive.aligned;" ::: "memory");
    asm volatile("barrier.cluster.wait.aligned;" ::: "memory");
}

// ============================ launch ============================
extern "C" void kernel_launch(void* const* d_in, const int* in_sizes, int n_in,
                              void* d_out, int out_size) {
    const float* X    = (const float*)d_in[0];   // [B, T, F] fp32
    const float* W    = (const float*)d_in[1];   // [S+F, S] fp32
    const float* bias = (const float*)d_in[2];   // [S] fp32
    float* out = (float*)d_out;

    // Kernel 1: out[b,t,:] = x[b,t,:] @ W_x + bias   (parallel GEMM into output buffer)
    dim3 g1(S_ / GBN, (B_ * T_) / GBM);
    gemm_u_kernel<<<g1, 256>>>(X, W, bias, out);

    // Kernel 2: in-place linear recurrence; one 2-CTA cluster per batch
    int write_final = (out_size >= B_ * T_ * S_ + B_ * S_) ? 1 : 0;
    dim3 g2(2, B_);
    recur_kernel<<<g2, 256>>>(W, out, write_final);
}